// round 8
// baseline (speedup 1.0000x reference)
#include <cuda_runtime.h>

typedef unsigned long long u64;

#define NBINS  4
#define NFEAT  48
#define KTOT   2048
#define NT     16            // batch rows per unit
#define TLEN   154
#define OUTF   (NBINS * NFEAT)
#define NCTAS  148
#define CHUNKK 512           // pooled k per chunk
#define SLOTF  (CHUNKK * 16) // floats per slot: 512 k * 16 n = 8192 (32KB)
#define NSLOTS 4
#define NTHREADS 768         // 16 consumer warps + 8 producer warps

// named barrier ids: full[s] = 1+s, empty[s] = 5+s
#define BAR_SYNC(id)   asm volatile("bar.sync %0, %1;"   :: "r"(id), "r"(NTHREADS) : "memory")
#define BAR_ARRIVE(id) asm volatile("bar.arrive %0, %1;" :: "r"(id), "r"(NTHREADS) : "memory")

__device__ float g_Weff[NBINS * NFEAT * KTOT];  // [bf][k]

__constant__ float c_dec_lo[8] = {
    -0.010597401784997278f,  0.032883011666982945f,  0.030841381835986965f,
    -0.18703481171888114f,  -0.02798376941698385f,   0.6308807679295904f,
     0.7148465705525415f,    0.23037781330885523f };
__constant__ float c_dec_hi[8] = {
    -0.23037781330885523f,   0.7148465705525415f,   -0.6308807679295904f,
    -0.02798376941698385f,   0.18703481171888114f,   0.030841381835986965f,
    -0.032883011666982945f, -0.010597401784997278f };

__device__ __forceinline__ u64 ffma2(u64 a, u64 b, u64 c) {
    u64 d; asm("fma.rn.f32x2 %0, %1, %2, %3;" : "=l"(d) : "l"(a), "l"(b), "l"(c));
    return d;
}
__device__ __forceinline__ u64 fadd2(u64 a, u64 b) {
    u64 d; asm("add.rn.f32x2 %0, %1, %2;" : "=l"(d) : "l"(a), "l"(b));
    return d;
}
__device__ __forceinline__ u64 dup2(float x) {
    u64 d; asm("mov.b64 %0, {%1, %1};" : "=l"(d) : "f"(x));
    return d;
}
__device__ __forceinline__ float2 unpack2(u64 a) {
    float2 v; asm("mov.b64 {%0, %1}, %2;" : "=f"(v.x), "=f"(v.y) : "l"(a));
    return v;
}
__device__ __forceinline__ int refl(int r, int N) {
    if (r < 0) r = -r;
    else if (r >= N) r = 2 * N - 2 - r;
    return r;
}

// ============================================================
// Fused weight builder (unchanged; ~3us).
// ============================================================
__global__ void build_weff_fused(const float* __restrict__ conv_w) {
    __shared__ float A[68 * 16];
    __shared__ float B[38 * 16];
    __shared__ float Mt[TLEN * 16];
    __shared__ float Ws[TLEN * 16];
    const int tid = threadIdx.x;
    const int bf = blockIdx.x;
    const int kc = blockIdx.y;

    for (int i = tid; i < TLEN * 16; i += 256)
        Ws[i] = conv_w[(size_t)bf * (TLEN * 16) + i];

    const int sl = tid & 15;
    const int ip = tid >> 4;
    const int j  = kc * 16 + sl;

    for (int i = ip; i < 67; i += 16) {
        float a0 = 0.0f, a1 = 0.0f;
        #pragma unroll
        for (int u = 0; u < 8; ++u) {
            int r = refl(2 * i + u - 6, 128);
            if (r == j) { a0 += c_dec_lo[7 - u]; a1 += c_dec_hi[7 - u]; }
        }
        A[i * 16 + sl] = a0;
        Mt[(14 + i) * 16 + sl] = a1;
    }
    __syncthreads();
    for (int i = ip; i < 37; i += 16) {
        float a0 = 0.0f, a1 = 0.0f;
        #pragma unroll
        for (int u = 0; u < 8; ++u) {
            int r = refl(2 * i + u - 6, 67);
            float xv = A[r * 16 + sl];
            a0 += xv * c_dec_lo[7 - u];
            a1 += xv * c_dec_hi[7 - u];
        }
        B[i * 16 + sl] = a0;
        Mt[(81 + i) * 16 + sl] = a1;
    }
    __syncthreads();
    for (int i = ip; i < 22; i += 16) {
        float a0 = 0.0f, a1 = 0.0f;
        #pragma unroll
        for (int u = 0; u < 8; ++u) {
            int r = refl(2 * i + u - 6, 37);
            float xv = B[r * 16 + sl];
            a0 += xv * c_dec_lo[7 - u];
            a1 += xv * c_dec_hi[7 - u];
        }
        A[i * 16 + sl] = a0;
        Mt[(118 + i) * 16 + sl] = a1;
    }
    __syncthreads();
    for (int i = ip; i < 14; i += 16) {
        float a0 = 0.0f, a1 = 0.0f;
        #pragma unroll
        for (int u = 0; u < 8; ++u) {
            int r = refl(2 * i + u - 6, 22);
            float xv = A[r * 16 + sl];
            a0 += xv * c_dec_lo[7 - u];
            a1 += xv * c_dec_hi[7 - u];
        }
        Mt[i * 16 + sl] = a0;
        Mt[(140 + i) * 16 + sl] = a1;
    }
    __syncthreads();

    const int scol = tid >> 4;
    const int hw   = tid & 15;
    float acc = 0.0f;
    #pragma unroll 7
    for (int t = 0; t < TLEN; ++t)
        acc += Mt[t * 16 + scol] * Ws[t * 16 + hw];
    g_Weff[(size_t)bf * KTOT + kc * 256 + tid] = acc;
}

// ============================================================
// Producer: 8 warps (256 threads). One 512-k chunk x 16 n.
// Per np: 2+2 front-batched LDG.128, shfl-pool, one STS.128
// {a0,a1,c0,c1} per owner lane (k-pair, conflict-free).
// Slot layout (floats): buf[np*1024 + 2*k + hal], k0 even.
// ============================================================
__device__ __forceinline__ void produce(float* __restrict__ buf,
                                        const float* __restrict__ x,
                                        int b, int g, int ci,
                                        int ntot, int ptid)
{
    const int n0 = g * NT;
    #pragma unroll 1
    for (int np = 0; np < 8; ++np) {
        int ne = n0 + 2 * np;
        int no = ne + 1;
        if (ne >= ntot) ne = ntot - 1;
        if (no >= ntot) no = ntot - 1;
        const float4* xg0 = reinterpret_cast<const float4*>(
            x + ((size_t)ne * 512 + b * 128 + ci * 32) * 64);
        const float4* xg1 = reinterpret_cast<const float4*>(
            x + ((size_t)no * 512 + b * 128 + ci * 32) * 64);
        float* smp = buf + np * 1024;

        float4 v0[2], v1[2];
        #pragma unroll
        for (int r = 0; r < 2; ++r) {
            v0[r] = xg0[ptid + 256 * r];
            v1[r] = xg1[ptid + 256 * r];
        }
        #pragma unroll
        for (int r = 0; r < 2; ++r) {
            int slot = ptid + 256 * r;       // tl*16 + p*2 + half
            float a0 = fmaxf(v0[r].x, v0[r].y), c0 = fmaxf(v0[r].z, v0[r].w);
            float a1 = fmaxf(v1[r].x, v1[r].y), c1 = fmaxf(v1[r].z, v1[r].w);
            a0 = fmaxf(a0, __shfl_xor_sync(0xffffffffu, a0, 2));
            c0 = fmaxf(c0, __shfl_xor_sync(0xffffffffu, c0, 2));
            a1 = fmaxf(a1, __shfl_xor_sync(0xffffffffu, a1, 2));
            c1 = fmaxf(c1, __shfl_xor_sync(0xffffffffu, c1, 2));
            if ((slot & 2) == 0) {
                int tl = slot >> 4;               // 0..31
                int h  = (slot >> 2) & 3;
                int qh = slot & 1;
                int k0 = tl * 16 + h * 4 + 2 * qh;   // even, 0..510
                *reinterpret_cast<float4*>(smp + 2 * k0) =
                    make_float4(a0, a1, c0, c1);
            }
        }
    }
}

// ============================================================
// Main: persistent, warp-specialized, 4-slot named-barrier ring.
// 148 CTAs x 768 threads, 128KB smem.
// Consumers (warps 0..15): fg = warp&7 (6 feats), nhalf = warp>>3
//   (4 np planes) — each pooled word read by 8 warps, not 16.
// Producers (warps 16..23) run up to 3 chunks ahead.
// ============================================================
__global__ __launch_bounds__(NTHREADS, 1)
void dwt_main_kernel(const float* __restrict__ x,
                     const float* __restrict__ conv_b,
                     float* __restrict__ out, int ntot, int groups)
{
    extern __shared__ float sm[];  // NSLOTS * SLOTF floats
    const int tid  = threadIdx.x;
    const int warp = tid >> 5;
    const int lane = tid & 31;
    const int cta  = blockIdx.x;
    const int G    = gridDim.x;
    const int nunits = NBINS * groups;
    const int myUnits = (cta < nunits) ? ((nunits - 1 - cta) / G + 1) : 0;
    const int totalChunks = 4 * myUnits;

    const int fg    = warp & 7;        // feature group (6 feats)
    const int nhalf = warp >> 3;       // 0: planes 0..3, 1: planes 4..7

    u64 acc[6][4];
    #pragma unroll
    for (int f = 0; f < 6; ++f)
        #pragma unroll
        for (int p = 0; p < 4; ++p) acc[f][p] = 0ull;

    // prologue: consumers mark all slots empty
    if (warp < 16) {
        #pragma unroll
        for (int s = 0; s < NSLOTS; ++s) BAR_ARRIVE(5 + s);
    }

    if (warp >= 16) {
        // ================= producers =================
        const int ptid = tid - 512;
        for (int sc = 0; sc < totalChunks; ++sc) {
            const int slot = sc & 3;
            const int u  = cta + G * (sc >> 2);
            const int b  = u / groups;
            const int g  = u % groups;
            const int ci = sc & 3;
            BAR_SYNC(5 + slot);                 // wait empty
            produce(sm + slot * SLOTF, x, b, g, ci, ntot, ptid);
            BAR_ARRIVE(1 + slot);               // mark full
        }
    } else {
        // ================= consumers =================
        for (int sc = 0; sc < totalChunks; ++sc) {
            const int slot = sc & 3;
            const int u  = cta + G * (sc >> 2);
            const int b  = u / groups;
            const int g  = u % groups;
            const int ci = sc & 3;
            float* buf = sm + slot * SLOTF;

            BAR_SYNC(1 + slot);                 // wait full

            const float* Wb = g_Weff + ((size_t)(b * NFEAT + fg * 6)) * KTOT
                              + ci * CHUNKK + lane;
            const float* smk = buf + nhalf * 4 * 1024 + 2 * lane;

            float w0[6], w1[6];
            #pragma unroll
            for (int f = 0; f < 6; ++f) w0[f] = __ldg(Wb + f * KTOT);
            #pragma unroll
            for (int f = 0; f < 6; ++f) w1[f] = __ldg(Wb + f * KTOT + 32);

            #pragma unroll 1
            for (int jl = 0; jl < 16; jl += 2) {
                {   // even jl: use w0, prefetch jl+2
                    u64 p2[4];
                    #pragma unroll
                    for (int pl = 0; pl < 4; ++pl)
                        p2[pl] = *reinterpret_cast<const u64*>(
                            smk + pl * 1024 + 64 * jl);
                    float a0 = w0[0], a1 = w0[1], a2 = w0[2],
                          a3 = w0[3], a4 = w0[4], a5 = w0[5];
                    if (jl + 2 < 16) {
                        #pragma unroll
                        for (int f = 0; f < 6; ++f)
                            w0[f] = __ldg(Wb + f * KTOT + 32 * (jl + 2));
                    }
                    u64 d0 = dup2(a0), d1 = dup2(a1), d2 = dup2(a2),
                        d3 = dup2(a3), d4 = dup2(a4), d5 = dup2(a5);
                    #pragma unroll
                    for (int pl = 0; pl < 4; ++pl) {
                        acc[0][pl] = ffma2(d0, p2[pl], acc[0][pl]);
                        acc[1][pl] = ffma2(d1, p2[pl], acc[1][pl]);
                        acc[2][pl] = ffma2(d2, p2[pl], acc[2][pl]);
                        acc[3][pl] = ffma2(d3, p2[pl], acc[3][pl]);
                        acc[4][pl] = ffma2(d4, p2[pl], acc[4][pl]);
                        acc[5][pl] = ffma2(d5, p2[pl], acc[5][pl]);
                    }
                }
                {   // odd jl: use w1, prefetch jl+3
                    u64 p2[4];
                    #pragma unroll
                    for (int pl = 0; pl < 4; ++pl)
                        p2[pl] = *reinterpret_cast<const u64*>(
                            smk + pl * 1024 + 64 * (jl + 1));
                    float a0 = w1[0], a1 = w1[1], a2 = w1[2],
                          a3 = w1[3], a4 = w1[4], a5 = w1[5];
                    if (jl + 3 < 16) {
                        #pragma unroll
                        for (int f = 0; f < 6; ++f)
                            w1[f] = __ldg(Wb + f * KTOT + 32 * (jl + 3));
                    }
                    u64 d0 = dup2(a0), d1 = dup2(a1), d2 = dup2(a2),
                        d3 = dup2(a3), d4 = dup2(a4), d5 = dup2(a5);
                    #pragma unroll
                    for (int pl = 0; pl < 4; ++pl) {
                        acc[0][pl] = ffma2(d0, p2[pl], acc[0][pl]);
                        acc[1][pl] = ffma2(d1, p2[pl], acc[1][pl]);
                        acc[2][pl] = ffma2(d2, p2[pl], acc[2][pl]);
                        acc[3][pl] = ffma2(d3, p2[pl], acc[3][pl]);
                        acc[4][pl] = ffma2(d4, p2[pl], acc[4][pl]);
                        acc[5][pl] = ffma2(d5, p2[pl], acc[5][pl]);
                    }
                }
            }

            BAR_ARRIVE(5 + slot);               // mark empty (before epilogue!)

            if (ci == 3) {
                // ---- epilogue: butterfly reduce + store + reset ----
                #pragma unroll
                for (int off = 16; off; off >>= 1)
                    #pragma unroll
                    for (int f = 0; f < 6; ++f)
                        #pragma unroll
                        for (int pl = 0; pl < 4; ++pl)
                            acc[f][pl] = fadd2(acc[f][pl],
                                __shfl_xor_sync(0xffffffffu, acc[f][pl], off));
                if (lane == 0) {
                    int n0 = g * NT + nhalf * 8;
                    #pragma unroll
                    for (int f = 0; f < 6; ++f) {
                        int fgl = fg * 6 + f;
                        float bias = conv_b[b * NFEAT + fgl];
                        #pragma unroll
                        for (int pl = 0; pl < 4; ++pl) {
                            float2 v = unpack2(acc[f][pl]);
                            int na = n0 + 2 * pl;
                            float ya = v.x + bias; ya = (ya > 0.0f) ? ya : 0.02f * ya;
                            float yb = v.y + bias; yb = (yb > 0.0f) ? yb : 0.02f * yb;
                            if (na < ntot)
                                out[(size_t)na * OUTF + b * NFEAT + fgl] = ya;
                            if (na + 1 < ntot)
                                out[(size_t)(na + 1) * OUTF + b * NFEAT + fgl] = yb;
                        }
                    }
                }
                #pragma unroll
                for (int f = 0; f < 6; ++f)
                    #pragma unroll
                    for (int pl = 0; pl < 4; ++pl) acc[f][pl] = 0ull;
            }
        }
    }
}

// ============================================================
extern "C" void kernel_launch(void* const* d_in, const int* in_sizes, int n_in,
                              void* d_out, int out_size)
{
    const float* x      = (const float*)d_in[0];  // (n,1,512,8,8)
    const float* conv_w = (const float*)d_in[1];  // (4,48,154,4,4)
    const float* conv_b = (const float*)d_in[2];  // (4,48)
    float* out = (float*)d_out;                   // (n,192)

    int ntot   = in_sizes[0] / (512 * 64);
    int groups = (ntot + NT - 1) / NT;

    dim3 wgrid(NBINS * NFEAT, KTOT / 256);
    build_weff_fused<<<wgrid, 256>>>(conv_w);

    cudaFuncSetAttribute(dwt_main_kernel,
                         cudaFuncAttributeMaxDynamicSharedMemorySize,
                         NSLOTS * SLOTF * 4);
    dwt_main_kernel<<<NCTAS, NTHREADS, NSLOTS * SLOTF * 4>>>(x, conv_b, out, ntot, groups);
}

// round 9
// speedup vs baseline: 1.4476x; 1.4476x over previous
#include <cuda_runtime.h>

typedef unsigned long long u64;

#define NBINS  4
#define NFEAT  48
#define KTOT   2048
#define NT     16            // batch rows per unit
#define TLEN   154
#define OUTF   (NBINS * NFEAT)
#define NCTAS  148
#define CHUNKK 512           // pooled k per chunk
#define SLOTF  (CHUNKK * 16) // floats per slot: 512 k * 16 n = 8192 (32KB)
#define NSLOTS 4
#define NTHREADS 768         // 16 consumer warps + 8 producer warps

// named barrier ids: full[s] = 1+s, empty[s] = 5+s
#define BAR_SYNC(id)   asm volatile("bar.sync %0, %1;"   :: "r"(id), "r"(NTHREADS) : "memory")
#define BAR_ARRIVE(id) asm volatile("bar.arrive %0, %1;" :: "r"(id), "r"(NTHREADS) : "memory")

__device__ float g_Weff[NBINS * NFEAT * KTOT];  // [bf][k]

__constant__ float c_dec_lo[8] = {
    -0.010597401784997278f,  0.032883011666982945f,  0.030841381835986965f,
    -0.18703481171888114f,  -0.02798376941698385f,   0.6308807679295904f,
     0.7148465705525415f,    0.23037781330885523f };
__constant__ float c_dec_hi[8] = {
    -0.23037781330885523f,   0.7148465705525415f,   -0.6308807679295904f,
    -0.02798376941698385f,   0.18703481171888114f,   0.030841381835986965f,
    -0.032883011666982945f, -0.010597401784997278f };

__device__ __forceinline__ u64 ffma2(u64 a, u64 b, u64 c) {
    u64 d; asm("fma.rn.f32x2 %0, %1, %2, %3;" : "=l"(d) : "l"(a), "l"(b), "l"(c));
    return d;
}
__device__ __forceinline__ u64 fadd2(u64 a, u64 b) {
    u64 d; asm("add.rn.f32x2 %0, %1, %2;" : "=l"(d) : "l"(a), "l"(b));
    return d;
}
__device__ __forceinline__ u64 dup2(float x) {
    u64 d; asm("mov.b64 %0, {%1, %1};" : "=l"(d) : "f"(x));
    return d;
}
__device__ __forceinline__ float2 unpack2(u64 a) {
    float2 v; asm("mov.b64 {%0, %1}, %2;" : "=f"(v.x), "=f"(v.y) : "l"(a));
    return v;
}
__device__ __forceinline__ int refl(int r, int N) {
    if (r < 0) r = -r;
    else if (r >= N) r = 2 * N - 2 - r;
    return r;
}

// ============================================================
// Fused weight builder (unchanged; ~3us).
// ============================================================
__global__ void build_weff_fused(const float* __restrict__ conv_w) {
    __shared__ float A[68 * 16];
    __shared__ float B[38 * 16];
    __shared__ float Mt[TLEN * 16];
    __shared__ float Ws[TLEN * 16];
    const int tid = threadIdx.x;
    const int bf = blockIdx.x;
    const int kc = blockIdx.y;

    for (int i = tid; i < TLEN * 16; i += 256)
        Ws[i] = conv_w[(size_t)bf * (TLEN * 16) + i];

    const int sl = tid & 15;
    const int ip = tid >> 4;
    const int j  = kc * 16 + sl;

    for (int i = ip; i < 67; i += 16) {
        float a0 = 0.0f, a1 = 0.0f;
        #pragma unroll
        for (int u = 0; u < 8; ++u) {
            int r = refl(2 * i + u - 6, 128);
            if (r == j) { a0 += c_dec_lo[7 - u]; a1 += c_dec_hi[7 - u]; }
        }
        A[i * 16 + sl] = a0;
        Mt[(14 + i) * 16 + sl] = a1;
    }
    __syncthreads();
    for (int i = ip; i < 37; i += 16) {
        float a0 = 0.0f, a1 = 0.0f;
        #pragma unroll
        for (int u = 0; u < 8; ++u) {
            int r = refl(2 * i + u - 6, 67);
            float xv = A[r * 16 + sl];
            a0 += xv * c_dec_lo[7 - u];
            a1 += xv * c_dec_hi[7 - u];
        }
        B[i * 16 + sl] = a0;
        Mt[(81 + i) * 16 + sl] = a1;
    }
    __syncthreads();
    for (int i = ip; i < 22; i += 16) {
        float a0 = 0.0f, a1 = 0.0f;
        #pragma unroll
        for (int u = 0; u < 8; ++u) {
            int r = refl(2 * i + u - 6, 37);
            float xv = B[r * 16 + sl];
            a0 += xv * c_dec_lo[7 - u];
            a1 += xv * c_dec_hi[7 - u];
        }
        A[i * 16 + sl] = a0;
        Mt[(118 + i) * 16 + sl] = a1;
    }
    __syncthreads();
    for (int i = ip; i < 14; i += 16) {
        float a0 = 0.0f, a1 = 0.0f;
        #pragma unroll
        for (int u = 0; u < 8; ++u) {
            int r = refl(2 * i + u - 6, 22);
            float xv = A[r * 16 + sl];
            a0 += xv * c_dec_lo[7 - u];
            a1 += xv * c_dec_hi[7 - u];
        }
        Mt[i * 16 + sl] = a0;
        Mt[(140 + i) * 16 + sl] = a1;
    }
    __syncthreads();

    const int scol = tid >> 4;
    const int hw   = tid & 15;
    float acc = 0.0f;
    #pragma unroll 7
    for (int t = 0; t < TLEN; ++t)
        acc += Mt[t * 16 + scol] * Ws[t * 16 + hw];
    g_Weff[(size_t)bf * KTOT + kc * 256 + tid] = acc;
}

// ============================================================
// Producer helpers: wave-batched fills (4 np per wave -> 16
// front-batched LDG.128 in flight, then pool+store the wave).
// Slot layout (floats): buf[np*1024 + 2*k + hal], k0 even.
// ============================================================
__device__ __forceinline__ void ldnp(const float* __restrict__ x,
                                     int b, int g, int ci, int ntot,
                                     int ptid, int np,
                                     float4* v0, float4* v1)
{
    int ne = g * NT + 2 * np;
    int no = ne + 1;
    if (ne >= ntot) ne = ntot - 1;
    if (no >= ntot) no = ntot - 1;
    const float4* xg0 = reinterpret_cast<const float4*>(
        x + ((size_t)ne * 512 + b * 128 + ci * 32) * 64);
    const float4* xg1 = reinterpret_cast<const float4*>(
        x + ((size_t)no * 512 + b * 128 + ci * 32) * 64);
    v0[0] = xg0[ptid];       v0[1] = xg0[ptid + 256];
    v1[0] = xg1[ptid];       v1[1] = xg1[ptid + 256];
}

__device__ __forceinline__ void poolstore(float* __restrict__ smp, int ptid,
                                          const float4* v0, const float4* v1)
{
    #pragma unroll
    for (int r = 0; r < 2; ++r) {
        int slot = ptid + 256 * r;       // tl*16 + p*2 + half
        float a0 = fmaxf(v0[r].x, v0[r].y), c0 = fmaxf(v0[r].z, v0[r].w);
        float a1 = fmaxf(v1[r].x, v1[r].y), c1 = fmaxf(v1[r].z, v1[r].w);
        a0 = fmaxf(a0, __shfl_xor_sync(0xffffffffu, a0, 2));
        c0 = fmaxf(c0, __shfl_xor_sync(0xffffffffu, c0, 2));
        a1 = fmaxf(a1, __shfl_xor_sync(0xffffffffu, a1, 2));
        c1 = fmaxf(c1, __shfl_xor_sync(0xffffffffu, c1, 2));
        if ((slot & 2) == 0) {
            int tl = slot >> 4;
            int h  = (slot >> 2) & 3;
            int qh = slot & 1;
            int k0 = tl * 16 + h * 4 + 2 * qh;   // even, 0..510
            *reinterpret_cast<float4*>(smp + 2 * k0) =
                make_float4(a0, a1, c0, c1);
        }
    }
}

__device__ __forceinline__ void produce(float* __restrict__ buf,
                                        const float* __restrict__ x,
                                        int b, int g, int ci,
                                        int ntot, int ptid)
{
    #pragma unroll
    for (int wv = 0; wv < 2; ++wv) {
        float4 v0[4][2], v1[4][2];
        // front-batched: 16 LDG.128 in flight before any pooling
        #pragma unroll
        for (int i = 0; i < 4; ++i)
            ldnp(x, b, g, ci, ntot, ptid, wv * 4 + i, v0[i], v1[i]);
        #pragma unroll
        for (int i = 0; i < 4; ++i)
            poolstore(buf + (wv * 4 + i) * 1024, ptid, v0[i], v1[i]);
    }
}

// ============================================================
// Main: persistent, warp-specialized, 4-slot named-barrier ring.
// 148 CTAs x 768 threads, 128KB smem.
// Warps 0..15: consumers (3 feats each, all 8 np planes);
// warps 16..23: producers (wave-batched). Producers run up to
// 3 chunks ahead. Unit = (b,g) = 16 batch rows, 4 chunks of 512 k.
// ============================================================
__global__ __launch_bounds__(NTHREADS, 1)
void dwt_main_kernel(const float* __restrict__ x,
                     const float* __restrict__ conv_b,
                     float* __restrict__ out, int ntot, int groups)
{
    extern __shared__ float sm[];  // NSLOTS * SLOTF floats
    const int tid  = threadIdx.x;
    const int warp = tid >> 5;
    const int lane = tid & 31;
    const int cta  = blockIdx.x;
    const int G    = gridDim.x;
    const int nunits = NBINS * groups;
    const int myUnits = (cta < nunits) ? ((nunits - 1 - cta) / G + 1) : 0;
    const int totalChunks = 4 * myUnits;

    u64 acc[3][8];
    #pragma unroll
    for (int f = 0; f < 3; ++f)
        #pragma unroll
        for (int p = 0; p < 8; ++p) acc[f][p] = 0ull;

    // prologue: consumers mark all slots empty
    if (warp < 16) {
        #pragma unroll
        for (int s = 0; s < NSLOTS; ++s) BAR_ARRIVE(5 + s);
    }

    if (warp >= 16) {
        // ================= producers =================
        const int ptid = tid - 512;
        for (int sc = 0; sc < totalChunks; ++sc) {
            const int slot = sc & 3;
            const int u  = cta + G * (sc >> 2);
            const int b  = u / groups;
            const int g  = u % groups;
            const int ci = sc & 3;
            BAR_SYNC(5 + slot);                 // wait empty
            produce(sm + slot * SLOTF, x, b, g, ci, ntot, ptid);
            BAR_ARRIVE(1 + slot);               // mark full
        }
    } else {
        // ================= consumers =================
        for (int sc = 0; sc < totalChunks; ++sc) {
            const int slot = sc & 3;
            const int u  = cta + G * (sc >> 2);
            const int b  = u / groups;
            const int g  = u % groups;
            const int ci = sc & 3;
            float* buf = sm + slot * SLOTF;

            BAR_SYNC(1 + slot);                 // wait full

            const float* Wb = g_Weff + ((size_t)(b * NFEAT + warp * 3)) * KTOT
                              + ci * CHUNKK + lane;
            const float* smk = buf + 2 * lane;

            float w0[3], w1[3];
            #pragma unroll
            for (int f = 0; f < 3; ++f) w0[f] = __ldg(Wb + f * KTOT);
            #pragma unroll
            for (int f = 0; f < 3; ++f) w1[f] = __ldg(Wb + f * KTOT + 32);

            #pragma unroll 1
            for (int jl = 0; jl < 16; jl += 2) {
                {   // even jl: use w0, prefetch jl+2
                    u64 p2[8];
                    #pragma unroll
                    for (int pl = 0; pl < 8; ++pl)
                        p2[pl] = *reinterpret_cast<const u64*>(
                            smk + pl * 1024 + 64 * jl);
                    float a0 = w0[0], a1 = w0[1], a2 = w0[2];
                    if (jl + 2 < 16) {
                        #pragma unroll
                        for (int f = 0; f < 3; ++f)
                            w0[f] = __ldg(Wb + f * KTOT + 32 * (jl + 2));
                    }
                    u64 d0 = dup2(a0), d1 = dup2(a1), d2 = dup2(a2);
                    #pragma unroll
                    for (int pl = 0; pl < 8; ++pl) {
                        acc[0][pl] = ffma2(d0, p2[pl], acc[0][pl]);
                        acc[1][pl] = ffma2(d1, p2[pl], acc[1][pl]);
                        acc[2][pl] = ffma2(d2, p2[pl], acc[2][pl]);
                    }
                }
                {   // odd jl: use w1, prefetch jl+3
                    u64 p2[8];
                    #pragma unroll
                    for (int pl = 0; pl < 8; ++pl)
                        p2[pl] = *reinterpret_cast<const u64*>(
                            smk + pl * 1024 + 64 * (jl + 1));
                    float a0 = w1[0], a1 = w1[1], a2 = w1[2];
                    if (jl + 3 < 16) {
                        #pragma unroll
                        for (int f = 0; f < 3; ++f)
                            w1[f] = __ldg(Wb + f * KTOT + 32 * (jl + 3));
                    }
                    u64 d0 = dup2(a0), d1 = dup2(a1), d2 = dup2(a2);
                    #pragma unroll
                    for (int pl = 0; pl < 8; ++pl) {
                        acc[0][pl] = ffma2(d0, p2[pl], acc[0][pl]);
                        acc[1][pl] = ffma2(d1, p2[pl], acc[1][pl]);
                        acc[2][pl] = ffma2(d2, p2[pl], acc[2][pl]);
                    }
                }
            }

            BAR_ARRIVE(5 + slot);               // mark empty (before epilogue!)

            if (ci == 3) {
                // ---- epilogue: butterfly reduce + store + reset ----
                #pragma unroll
                for (int off = 16; off; off >>= 1)
                    #pragma unroll
                    for (int f = 0; f < 3; ++f)
                        #pragma unroll
                        for (int pl = 0; pl < 8; ++pl)
                            acc[f][pl] = fadd2(acc[f][pl],
                                __shfl_xor_sync(0xffffffffu, acc[f][pl], off));
                if (lane == 0) {
                    int n0 = g * NT;
                    #pragma unroll
                    for (int f = 0; f < 3; ++f) {
                        int fgl = warp * 3 + f;
                        float bias = conv_b[b * NFEAT + fgl];
                        #pragma unroll
                        for (int pl = 0; pl < 8; ++pl) {
                            float2 v = unpack2(acc[f][pl]);
                            int na = n0 + 2 * pl;
                            float ya = v.x + bias; ya = (ya > 0.0f) ? ya : 0.02f * ya;
                            float yb = v.y + bias; yb = (yb > 0.0f) ? yb : 0.02f * yb;
                            if (na < ntot)
                                out[(size_t)na * OUTF + b * NFEAT + fgl] = ya;
                            if (na + 1 < ntot)
                                out[(size_t)(na + 1) * OUTF + b * NFEAT + fgl] = yb;
                        }
                    }
                }
                #pragma unroll
                for (int f = 0; f < 3; ++f)
                    #pragma unroll
                    for (int pl = 0; pl < 8; ++pl) acc[f][pl] = 0ull;
            }
        }
    }
}

// ============================================================
extern "C" void kernel_launch(void* const* d_in, const int* in_sizes, int n_in,
                              void* d_out, int out_size)
{
    const float* x      = (const float*)d_in[0];  // (n,1,512,8,8)
    const float* conv_w = (const float*)d_in[1];  // (4,48,154,4,4)
    const float* conv_b = (const float*)d_in[2];  // (4,48)
    float* out = (float*)d_out;                   // (n,192)

    int ntot   = in_sizes[0] / (512 * 64);
    int groups = (ntot + NT - 1) / NT;

    dim3 wgrid(NBINS * NFEAT, KTOT / 256);
    build_weff_fused<<<wgrid, 256>>>(conv_w);

    cudaFuncSetAttribute(dwt_main_kernel,
                         cudaFuncAttributeMaxDynamicSharedMemorySize,
                         NSLOTS * SLOTF * 4);
    dwt_main_kernel<<<NCTAS, NTHREADS, NSLOTS * SLOTF * 4>>>(x, conv_b, out, ntot, groups);
}